// round 14
// baseline (speedup 1.0000x reference)
#include <cuda_runtime.h>
#include <cuda_fp16.h>
#include <stdint.h>
#include <math.h>

#define NB 8
#define NC 64
#define NH 64
#define NWD 64
#define NTOK (NH*NWD)
#define NGROUPS 32
#define CPG (NC/NGROUPS)
#define SP 80                  // smem row stride in halves (160B)
#define ONESH2 0x3C003C00u     // half2(1.0, 1.0)

// Scratch
__device__ __half g_qh[NB*NTOK*NC];      // (b, token, kperm(c)), x (0.125*log2e)
__device__ __half g_kh[NB*NTOK*NC];      // (b, token, kperm(c))
__device__ __half g_vTh[NB*NC*NTOK];     // (b, c, kperm-within-16(token))
__device__ float  g_mu[NB*NGROUPS];
__device__ float  g_rs[NB*NGROUPS];

// k-pair interleave within each 16-block: [0,1,8,9, 2,3,10,11, 4,5,12,13, 6,7,14,15]
__device__ __forceinline__ int perm16(int k) {
    return ((k & 7) >> 1) * 4 + (k & 1) + ((k >> 3) & 1) * 2;
}
__device__ __forceinline__ int kperm(int c) { return (c & ~15) | perm16(c & 15); }

__device__ __forceinline__ uint32_t ex2h2(uint32_t a) {
    uint32_t r; asm("ex2.approx.f16x2 %0, %1;" : "=r"(r) : "r"(a)); return r;
}

__device__ __forceinline__ void mma_f16(float* d, unsigned a0, unsigned a1,
                                        unsigned a2, unsigned a3,
                                        unsigned b0, unsigned b1) {
    asm volatile("mma.sync.aligned.m16n8k16.row.col.f32.f16.f16.f32 "
                 "{%0,%1,%2,%3}, {%4,%5,%6,%7}, {%8,%9}, {%0,%1,%2,%3};"
                 : "+f"(d[0]), "+f"(d[1]), "+f"(d[2]), "+f"(d[3])
                 : "r"(a0), "r"(a1), "r"(a2), "r"(a3), "r"(b0), "r"(b1));
}

__device__ __forceinline__ uint32_t smem_u32(const void* p) {
    uint32_t a;
    asm("{ .reg .u64 t; cvta.to.shared.u64 t, %1; cvt.u32.u64 %0, t; }" : "=r"(a) : "l"(p));
    return a;
}
__device__ __forceinline__ void cp_async16(uint32_t dst, const void* src) {
    asm volatile("cp.async.cg.shared.global [%0], [%1], 16;" :: "r"(dst), "l"(src));
}
#define CP_COMMIT() asm volatile("cp.async.commit_group;" ::: "memory")
#define CP_WAIT1()  asm volatile("cp.async.wait_group 1;" ::: "memory")

// ---------------------------------------------------------------------------
// Kernel 1: GroupNorm statistics (MLP-8 load batch).
// ---------------------------------------------------------------------------
__global__ void __launch_bounds__(256) gn_stats_kernel(const float* __restrict__ x) {
    int b = blockIdx.x >> 5;
    int g = blockIdx.x & 31;
    size_t base = ((size_t)(b*NC + g*CPG)) * (NH*NWD);
    const float* xp = x + base;
    int tid = threadIdx.x;

    float4 v[8];
    #pragma unroll
    for (int i = 0; i < 8; i++)
        v[i] = *(const float4*)(xp + tid*4 + i*1024);
    float s = 0.f, s2 = 0.f;
    #pragma unroll
    for (int i = 0; i < 8; i++) {
        s  += v[i].x + v[i].y + v[i].z + v[i].w;
        s2 += v[i].x*v[i].x + v[i].y*v[i].y + v[i].z*v[i].z + v[i].w*v[i].w;
    }

    __shared__ float rs[256], rq[256];
    rs[tid] = s; rq[tid] = s2;
    __syncthreads();
    for (int st = 128; st > 0; st >>= 1) {
        if (tid < st) { rs[tid] += rs[tid+st]; rq[tid] += rq[tid+st]; }
        __syncthreads();
    }
    if (tid == 0) {
        const float inv = 1.f / 8192.f;
        float m = rs[0] * inv;
        float var = rq[0] * inv - m*m;
        g_mu[blockIdx.x] = m;
        g_rs[blockIdx.x] = rsqrtf(var + 1e-5f);
    }
}

// ---------------------------------------------------------------------------
// Kernel 2: fused GN-apply + Q/K/V linears -> fp16 permuted layouts.
// ---------------------------------------------------------------------------
__global__ void __launch_bounds__(256) qkv_kernel(const float* __restrict__ x,
                                                  const float* __restrict__ gw, const float* __restrict__ gb,
                                                  const float* __restrict__ Wq, const float* __restrict__ bq,
                                                  const float* __restrict__ Wk, const float* __restrict__ bk,
                                                  const float* __restrict__ Wv, const float* __restrict__ bv) {
    __shared__ float Xs[4096];
    __shared__ float Ws[4096];
    __shared__ float bs[64];
    __shared__ float scs[64], shs[64];
    __shared__ __half Ss[64*72];

    int b = blockIdx.x >> 6;
    int h = blockIdx.x & 63;
    int tid = threadIdx.x;
    int ty = tid >> 4, tx = tid & 15;

    if (tid < 64) {
        float mu = g_mu[b*32 + (tid >> 1)];
        float rr = g_rs[b*32 + (tid >> 1)];
        float sc = gw[tid] * rr;
        scs[tid] = sc;
        shs[tid] = gb[tid] - mu * sc;
    }
    __syncthreads();

    for (int f = tid*4; f < 4096; f += 1024) {
        int c = f >> 6, w0 = f & 63;
        float4 v = *(const float4*)(x + ((((size_t)b*64 + c)*64 + h)*64 + w0));
        float sc = scs[c], sh = shs[c];
        float4 o;
        o.x = v.x*sc + sh; o.y = v.y*sc + sh; o.z = v.z*sc + sh; o.w = v.w*sc + sh;
        *(float4*)(Xs + f) = o;
    }

    const float* Wm[3] = {Wq, Wk, Wv};
    const float* bm[3] = {bq, bk, bv};

    for (int which = 0; which < 3; ++which) {
        __syncthreads();
        const float* Wg = Wm[which];
        for (int f = tid*4; f < 4096; f += 1024) {
            int j = f >> 6, w0 = f & 63;
            float4 v = *(const float4*)(Wg + f);
            int sw = j & 31;
            Ws[j*64 + ((w0+0)^sw)] = v.x;
            Ws[j*64 + ((w0+1)^sw)] = v.y;
            Ws[j*64 + ((w0+2)^sw)] = v.z;
            Ws[j*64 + ((w0+3)^sw)] = v.w;
        }
        if (tid < 64) bs[tid] = bm[which][tid];
        __syncthreads();

        float acc[4][4];
        #pragma unroll
        for (int i = 0; i < 4; i++)
            #pragma unroll
            for (int j = 0; j < 4; j++) acc[i][j] = 0.f;

        #pragma unroll 16
        for (int w = 0; w < 64; ++w) {
            float a[4], bb[4];
            #pragma unroll
            for (int i = 0; i < 4; i++) a[i] = Xs[(ty + 16*i)*64 + w];
            #pragma unroll
            for (int j = 0; j < 4; j++) { int jj = tx + 16*j; bb[j] = Ws[jj*64 + (w ^ (jj & 31))]; }
            #pragma unroll
            for (int i = 0; i < 4; i++)
                #pragma unroll
                for (int j = 0; j < 4; j++) acc[i][j] += a[i]*bb[j];
        }

        float sc = (which == 0) ? 0.125f * 1.4426950408889634f : 1.0f;
        #pragma unroll
        for (int j = 0; j < 4; j++) {
            int jj = tx + 16*j;
            float bias = bs[jj];
            #pragma unroll
            for (int i = 0; i < 4; i++) {
                int cc = ty + 16*i;
                __half v = __float2half_rn((acc[i][j] + bias) * sc);
                if (which < 2) Ss[jj*72 + kperm(cc)] = v;
                else           Ss[cc*72 + kperm(jj)] = v;
            }
        }
        __syncthreads();

        if (which < 2) {
            __half* og = (which == 0 ? g_qh : g_kh) + ((size_t)b*NTOK + h*64)*64;
            for (int idx = tid; idx < 512; idx += 256) {
                int r = idx >> 3, c8 = (idx & 7)*8;
                *(int4*)(og + r*64 + c8) = *(int4*)(Ss + r*72 + c8);
            }
        } else {
            __half* og = g_vTh + (size_t)b*NC*NTOK + h*64;
            for (int idx = tid; idx < 512; idx += 256) {
                int c = idx >> 3, t8 = (idx & 7)*8;
                *(int4*)(og + (size_t)c*NTOK + t8) = *(int4*)(Ss + c*72 + t8);
            }
        }
    }
}

// ---------------------------------------------------------------------------
// Kernel 3: flash attention, SPLIT-TOKEN tiling (512 threads, 16 warps):
// warp = (row-group of 16 q-rows, token-half of key tile). Q fragments held
// in registers for the entire kernel. Partial O/l summed in epilogue.
// Fixed-max exp2 softmax, l via ones-MMA, fused projection + residual.
// ---------------------------------------------------------------------------
#define QS_OFF 0
#define KS_OFF (128*SP)
#define VS_OFF (KS_OFF + 3*64*SP)
#define HALF_REGION (VS_OFF + 3*64*SP)          // 40960 halves = 81920 B
#define WP_OFF_B (HALF_REGION*2)
#define ATTN_SMEM (WP_OFF_B + (64*68 + 64 + 128)*4)

__global__ void __launch_bounds__(512, 1) attn_kernel(const float* __restrict__ x,
                                                      const float* __restrict__ Wp,
                                                      const float* __restrict__ bp,
                                                      float* __restrict__ out) {
    extern __shared__ __half smh[];
    uint32_t sb = smem_u32(smh);
    __half* Qs = smh + QS_OFF;
    float* Wps = (float*)((char*)smh + WP_OFF_B);      // [64][68]
    float* bps = Wps + 64*68;                          // [64]
    float* ls  = bps + 64;                             // [128]

    int b  = blockIdx.y;
    int q0 = blockIdx.x * 128;
    int tid = threadIdx.x;
    int lane = tid & 31, warp = tid >> 5;
    int rg = warp >> 1;            // row-group 0..7 -> rows 16rg..16rg+15
    int ch = warp & 1;             // token half 0..1
    int wm = rg * 16;
    int tc0 = ch * 32;             // warp's token offset within the key tile
    int gi = lane >> 2;
    int t4 = lane & 3;

    const __half* qb = g_qh  + ((size_t)b*NTOK + q0)*64;
    const __half* kb = g_kh  + (size_t)b*NTOK*64;
    const __half* vb = g_vTh + (size_t)b*NC*NTOK;

    // ---- Prologue group A: Q + Wp + bp + K0/V0
    for (int idx = tid; idx < 1024; idx += 512) {
        int r = idx >> 3, cB = (idx & 7)*16;
        cp_async16(sb + (QS_OFF + r*SP)*2 + cB, qb + r*64 + cB/2);
    }
    for (int idx = tid; idx < 1024; idx += 512) {
        int r = idx >> 4, cc = idx & 15;
        cp_async16(sb + WP_OFF_B + r*68*4 + cc*16, Wp + r*64 + cc*4);
    }
    if (tid < 16) cp_async16(sb + WP_OFF_B + 64*68*4 + tid*16, bp + tid*4);
    for (int idx = tid; idx < 1024; idx += 512) {
        int r = (idx >> 3) & 63, cB = (idx & 7)*16;
        if (idx < 512)
            cp_async16(sb + (KS_OFF + r*SP)*2 + cB, kb + (size_t)r*64 + cB/2);
        else
            cp_async16(sb + (VS_OFF + r*SP)*2 + cB, vb + (size_t)r*NTOK + cB/2);
    }
    CP_COMMIT();
    // ---- Prologue group B: K1/V1
    for (int idx = tid; idx < 1024; idx += 512) {
        int r = (idx >> 3) & 63, cB = (idx & 7)*16;
        if (idx < 512)
            cp_async16(sb + (KS_OFF + 64*SP + r*SP)*2 + cB, kb + (size_t)(64 + r)*64 + cB/2);
        else
            cp_async16(sb + (VS_OFF + 64*SP + r*SP)*2 + cB, vb + (size_t)r*NTOK + 64 + cB/2);
    }
    CP_COMMIT();

    // ---- wait for group A; hoist Q fragments into registers (whole kernel)
    CP_WAIT1();
    __syncthreads();
    uint2 qf0[4], qf1[4];          // [kstep] rows wm+gi / wm+gi+8
    #pragma unroll
    for (int k = 0; k < 4; ++k) {
        int off = k*16 + 4*t4;
        qf0[k] = *(const uint2*)(Qs + (wm + gi)*SP + off);
        qf1[k] = *(const uint2*)(Qs + (wm + gi + 8)*SP + off);
    }

    float o[8][4];
    #pragma unroll
    for (int j = 0; j < 8; j++) { o[j][0]=0.f; o[j][1]=0.f; o[j][2]=0.f; o[j][3]=0.f; }
    float lacc[4] = {0.f, 0.f, 0.f, 0.f};

    for (int kt = 0; kt < 64; ++kt) {
        CP_WAIT1();
        __syncthreads();

        if (kt + 2 < 64) {
            const __half* kp = kb + (size_t)((kt+2)*64)*64;
            const __half* vp = vb + (kt+2)*64;
            int buf = (kt + 2) % 3;
            for (int idx = tid; idx < 1024; idx += 512) {
                int r = (idx >> 3) & 63, cB = (idx & 7)*16;
                if (idx < 512)
                    cp_async16(sb + (KS_OFF + buf*64*SP + r*SP)*2 + cB, kp + (size_t)r*64 + cB/2);
                else
                    cp_async16(sb + (VS_OFF + buf*64*SP + r*SP)*2 + cB, vp + (size_t)r*NTOK + cB/2);
            }
        }
        CP_COMMIT();

        const __half* Kb = smh + KS_OFF + (kt % 3)*64*SP;
        const __half* Vb = smh + VS_OFF + (kt % 3)*64*SP;

        // ---- S = Q K^T for this warp's 16 rows x 32 tokens (4 n-tiles)
        float s[4][4];
        #pragma unroll
        for (int j = 0; j < 4; j++) { s[j][0]=0.f; s[j][1]=0.f; s[j][2]=0.f; s[j][3]=0.f; }
        #pragma unroll
        for (int k = 0; k < 4; ++k) {
            int off = k*16 + 4*t4;
            #pragma unroll
            for (int j = 0; j < 4; ++j) {
                uint2 bb = *(const uint2*)(Kb + (tc0 + j*8 + gi)*SP + off);
                mma_f16(s[j], qf0[k].x, qf1[k].x, qf0[k].y, qf1[k].y, bb.x, bb.y);
            }
        }

        // ---- P = exp2(S) -> half2 A-fragments
        uint32_t pa[4][2];
        #pragma unroll
        for (int j = 0; j < 4; j++) {
            __half2 h0 = __floats2half2_rn(s[j][0], s[j][1]);
            __half2 h1 = __floats2half2_rn(s[j][2], s[j][3]);
            pa[j][0] = ex2h2(*(uint32_t*)&h0);
            pa[j][1] = ex2h2(*(uint32_t*)&h1);
        }

        // ---- O += P V over this warp's 32 tokens (2 A-ktiles); l ones-MMA
        #pragma unroll
        for (int kk = 0; kk < 2; ++kk) {
            int off = tc0 + kk*16 + 4*t4;
            #pragma unroll
            for (int jc = 0; jc < 8; ++jc) {
                uint2 bb = *(const uint2*)(Vb + (jc*8 + gi)*SP + off);
                mma_f16(o[jc], pa[2*kk][0], pa[2*kk][1], pa[2*kk+1][0], pa[2*kk+1][1], bb.x, bb.y);
            }
            mma_f16(lacc, pa[2*kk][0], pa[2*kk][1], pa[2*kk+1][0], pa[2*kk+1][1], ONESH2, ONESH2);
        }
    }

    // ======= epilogue: reduce token-halves, normalize, fused projection ======
    float* As = (float*)smh;             // [128][68] overlays Q/K rings

    __syncthreads();   // all K/V/Q smem reads done; safe to overlay
    if (ch == 0) {
        #pragma unroll
        for (int j = 0; j < 8; j++) {
            int c = j*8 + 2*t4;
            *(float2*)(As + (wm + gi)*68 + c)     = make_float2(o[j][0], o[j][1]);
            *(float2*)(As + (wm + gi + 8)*68 + c) = make_float2(o[j][2], o[j][3]);
        }
        if (t4 == 0) { ls[wm + gi] = lacc[0]; ls[wm + gi + 8] = lacc[2]; }
    }
    __syncthreads();
    if (ch == 1) {
        #pragma unroll
        for (int j = 0; j < 8; j++) {
            int c = j*8 + 2*t4;
            float2 v0 = *(float2*)(As + (wm + gi)*68 + c);
            float2 v1 = *(float2*)(As + (wm + gi + 8)*68 + c);
            v0.x += o[j][0]; v0.y += o[j][1];
            v1.x += o[j][2]; v1.y += o[j][3];
            *(float2*)(As + (wm + gi)*68 + c)     = v0;
            *(float2*)(As + (wm + gi + 8)*68 + c) = v1;
        }
        if (t4 == 0) { ls[wm + gi] += lacc[0]; ls[wm + gi + 8] += lacc[2]; }
    }
    __syncthreads();
    if (tid < 128) ls[tid] = 1.f / ls[tid];
    __syncthreads();
    for (int i = tid*4; i < 8192; i += 2048) {      // normalize As rows
        int r = i >> 6, c = i & 63;
        float rl = ls[r];
        float4 v = *(float4*)(As + r*68 + c);
        v.x *= rl; v.y *= rl; v.z *= rl; v.w *= rl;
        *(float4*)(As + r*68 + c) = v;
    }
    __syncthreads();

    // fused projection + residual (two h-rows; 256 threads each)
    int hs = tid >> 8;
    int tl = tid & 255;
    int ty = tl >> 4, tx = tl & 15;
    int h0 = q0 >> 6;
    {
        float acc[4][4];
        #pragma unroll
        for (int i = 0; i < 4; i++)
            #pragma unroll
            for (int j = 0; j < 4; j++) acc[i][j] = 0.f;

        #pragma unroll 16
        for (int w = 0; w < 64; ++w) {
            float a[4], bb[4];
            #pragma unroll
            for (int i = 0; i < 4; i++) a[i] = As[(hs*64 + w)*68 + (ty + 16*i)];
            #pragma unroll
            for (int j = 0; j < 4; j++) { int jj = tx + 16*j; bb[j] = Wps[jj*68 + w]; }
            #pragma unroll
            for (int i = 0; i < 4; i++)
                #pragma unroll
                for (int j = 0; j < 4; j++) acc[i][j] += a[i]*bb[j];
        }

        int h = h0 + hs;
        #pragma unroll
        for (int j = 0; j < 4; j++) {
            int jj = tx + 16*j;
            float bias = bps[jj];
            #pragma unroll
            for (int i = 0; i < 4; i++) {
                int cc = ty + 16*i;
                size_t oidx = (((size_t)b*64 + cc)*64 + h)*64 + jj;
                out[oidx] = acc[i][j] + bias + x[oidx];
            }
        }
    }
}

// ---------------------------------------------------------------------------
extern "C" void kernel_launch(void* const* d_in, const int* in_sizes, int n_in,
                              void* d_out, int out_size) {
    const float* x   = (const float*)d_in[0];
    const float* gnw = (const float*)d_in[1];
    const float* gnb = (const float*)d_in[2];
    const float* Wq  = (const float*)d_in[3];
    const float* bq  = (const float*)d_in[4];
    const float* Wk  = (const float*)d_in[5];
    const float* bk  = (const float*)d_in[6];
    const float* Wv  = (const float*)d_in[7];
    const float* bv  = (const float*)d_in[8];
    const float* Wp  = (const float*)d_in[9];
    const float* bp  = (const float*)d_in[10];
    float* out = (float*)d_out;

    cudaFuncSetAttribute(attn_kernel, cudaFuncAttributeMaxDynamicSharedMemorySize, ATTN_SMEM);

    gn_stats_kernel<<<NB*NGROUPS, 256>>>(x);
    qkv_kernel<<<NB*NH, 256>>>(x, gnw, gnb, Wq, bq, Wk, bk, Wv, bv);
    attn_kernel<<<dim3(NTOK/128, NB), 512, ATTN_SMEM>>>(x, Wp, bp, out);
}

// round 15
// speedup vs baseline: 1.2345x; 1.2345x over previous
#include <cuda_runtime.h>
#include <cuda_fp16.h>
#include <stdint.h>
#include <math.h>

#define NB 8
#define NC 64
#define NH 64
#define NWD 64
#define NTOK (NH*NWD)
#define NGROUPS 32
#define CPG (NC/NGROUPS)
#define SP 80                  // smem row stride in halves (160B)

// Scratch
__device__ __half g_qh[NB*NTOK*NC];      // (b, token, kperm(c)), x (0.125*log2e)
__device__ __half g_kh[NB*NTOK*NC];      // (b, token, kperm(c))
__device__ __half g_vTh[NB*NC*NTOK];     // (b, c, kperm-within-16(token))
__device__ float  g_mu[NB*NGROUPS];
__device__ float  g_rs[NB*NGROUPS];

// k-pair interleave within each 16-block: [0,1,8,9, 2,3,10,11, 4,5,12,13, 6,7,14,15]
__device__ __forceinline__ int perm16(int k) {
    return ((k & 7) >> 1) * 4 + (k & 1) + ((k >> 3) & 1) * 2;
}
__device__ __forceinline__ int kperm(int c) { return (c & ~15) | perm16(c & 15); }

__device__ __forceinline__ uint32_t ex2h2(uint32_t a) {
    uint32_t r; asm("ex2.approx.f16x2 %0, %1;" : "=r"(r) : "r"(a)); return r;
}

__device__ __forceinline__ void mma_f16(float* d, unsigned a0, unsigned a1,
                                        unsigned a2, unsigned a3,
                                        unsigned b0, unsigned b1) {
    asm volatile("mma.sync.aligned.m16n8k16.row.col.f32.f16.f16.f32 "
                 "{%0,%1,%2,%3}, {%4,%5,%6,%7}, {%8,%9}, {%0,%1,%2,%3};"
                 : "+f"(d[0]), "+f"(d[1]), "+f"(d[2]), "+f"(d[3])
                 : "r"(a0), "r"(a1), "r"(a2), "r"(a3), "r"(b0), "r"(b1));
}

__device__ __forceinline__ uint32_t smem_u32(const void* p) {
    uint32_t a;
    asm("{ .reg .u64 t; cvta.to.shared.u64 t, %1; cvt.u32.u64 %0, t; }" : "=r"(a) : "l"(p));
    return a;
}
__device__ __forceinline__ void cp_async16(uint32_t dst, const void* src) {
    asm volatile("cp.async.cg.shared.global [%0], [%1], 16;" :: "r"(dst), "l"(src));
}
#define CP_COMMIT() asm volatile("cp.async.commit_group;" ::: "memory")
#define CP_WAIT1()  asm volatile("cp.async.wait_group 1;" ::: "memory")

// ---------------------------------------------------------------------------
// Kernel 1: GroupNorm statistics (MLP-8 load batch).
// ---------------------------------------------------------------------------
__global__ void __launch_bounds__(256) gn_stats_kernel(const float* __restrict__ x) {
    int b = blockIdx.x >> 5;
    int g = blockIdx.x & 31;
    size_t base = ((size_t)(b*NC + g*CPG)) * (NH*NWD);
    const float* xp = x + base;
    int tid = threadIdx.x;

    float4 v[8];
    #pragma unroll
    for (int i = 0; i < 8; i++)
        v[i] = *(const float4*)(xp + tid*4 + i*1024);
    float s = 0.f, s2 = 0.f;
    #pragma unroll
    for (int i = 0; i < 8; i++) {
        s  += v[i].x + v[i].y + v[i].z + v[i].w;
        s2 += v[i].x*v[i].x + v[i].y*v[i].y + v[i].z*v[i].z + v[i].w*v[i].w;
    }

    __shared__ float rs[256], rq[256];
    rs[tid] = s; rq[tid] = s2;
    __syncthreads();
    for (int st = 128; st > 0; st >>= 1) {
        if (tid < st) { rs[tid] += rs[tid+st]; rq[tid] += rq[tid+st]; }
        __syncthreads();
    }
    if (tid == 0) {
        const float inv = 1.f / 8192.f;
        float m = rs[0] * inv;
        float var = rq[0] * inv - m*m;
        g_mu[blockIdx.x] = m;
        g_rs[blockIdx.x] = rsqrtf(var + 1e-5f);
    }
}

// ---------------------------------------------------------------------------
// Kernel 2: fused GN-apply + Q/K/V linears on mma.16816 (fp16 X and W).
// Per CTA (b,h): Xh[64c][kperm(w)] fp16, loop over {Wq,Wk,Wv}.
// Warp (mt = warp&3: c-rows 16mt..; nh = warp>>2: j-cols 32nh..).
// ---------------------------------------------------------------------------
__global__ void __launch_bounds__(256) qkv_kernel(const float* __restrict__ x,
                                                  const float* __restrict__ gw, const float* __restrict__ gb,
                                                  const float* __restrict__ Wq, const float* __restrict__ bq,
                                                  const float* __restrict__ Wk, const float* __restrict__ bk,
                                                  const float* __restrict__ Wv, const float* __restrict__ bv) {
    __shared__ __half Xh[64*SP];
    __shared__ __half Wh[64*SP];
    __shared__ __half Ss[64*72];
    __shared__ float bs[64];
    __shared__ float scs[64], shs[64];

    int b = blockIdx.x >> 6;
    int h = blockIdx.x & 63;
    int tid = threadIdx.x;
    int lane = tid & 31, warp = tid >> 5;
    int mt = warp & 3;            // c-row tile: rows 16mt..16mt+15
    int nh = warp >> 2;           // j half: cols 32nh..32nh+31
    int gi = lane >> 2, t4 = lane & 3;

    if (tid < 64) {
        float mu = g_mu[b*32 + (tid >> 1)];
        float rr = g_rs[b*32 + (tid >> 1)];
        float sc = gw[tid] * rr;
        scs[tid] = sc;
        shs[tid] = gb[tid] - mu * sc;
    }
    __syncthreads();

    // Stage X: normalize + cvt fp16 + kperm columns (pairs stay adjacent)
    for (int f = tid*4; f < 4096; f += 1024) {
        int c = f >> 6, w0 = f & 63;
        float4 v = *(const float4*)(x + ((((size_t)b*64 + c)*64 + h)*64 + w0));
        float sc = scs[c], sh = shs[c];
        __half2 p0 = __floats2half2_rn(v.x*sc + sh, v.y*sc + sh);
        __half2 p1 = __floats2half2_rn(v.z*sc + sh, v.w*sc + sh);
        *(__half2*)(Xh + c*SP + kperm(w0))     = p0;
        *(__half2*)(Xh + c*SP + kperm(w0 + 2)) = p1;
    }

    const float* Wm[3] = {Wq, Wk, Wv};
    const float* bm[3] = {bq, bk, bv};

    for (int which = 0; which < 3; ++which) {
        __syncthreads();    // Xh ready / previous copy-out of Ss done, Wh free
        const float* Wg = Wm[which];
        for (int f = tid*4; f < 4096; f += 1024) {
            int j = f >> 6, w0 = f & 63;
            float4 v = *(const float4*)(Wg + f);
            *(__half2*)(Wh + j*SP + kperm(w0))     = __floats2half2_rn(v.x, v.y);
            *(__half2*)(Wh + j*SP + kperm(w0 + 2)) = __floats2half2_rn(v.z, v.w);
        }
        if (tid < 64) bs[tid] = bm[which][tid];
        __syncthreads();

        float s[4][4];
        #pragma unroll
        for (int j = 0; j < 4; j++) { s[j][0]=0.f; s[j][1]=0.f; s[j][2]=0.f; s[j][3]=0.f; }
        #pragma unroll
        for (int k = 0; k < 4; ++k) {
            int off = k*16 + 4*t4;
            uint2 a0 = *(const uint2*)(Xh + (mt*16 + gi)*SP + off);
            uint2 a1 = *(const uint2*)(Xh + (mt*16 + gi + 8)*SP + off);
            #pragma unroll
            for (int j = 0; j < 4; ++j) {
                uint2 bb = *(const uint2*)(Wh + (nh*32 + j*8 + gi)*SP + off);
                mma_f16(s[j], a0.x, a1.x, a0.y, a1.y, bb.x, bb.y);
            }
        }

        float sc = (which == 0) ? 0.125f * 1.4426950408889634f : 1.0f;
        #pragma unroll
        for (int j = 0; j < 4; ++j) {
            int col0 = nh*32 + j*8 + 2*t4;       // output token index (pair)
            int r0 = mt*16 + gi, r1 = r0 + 8;    // output channel rows
            float v00 = (s[j][0] + bs[col0])   * sc;
            float v01 = (s[j][1] + bs[col0+1]) * sc;
            float v10 = (s[j][2] + bs[col0])   * sc;
            float v11 = (s[j][3] + bs[col0+1]) * sc;
            if (which < 2) {
                Ss[(col0    )*72 + kperm(r0)] = __float2half_rn(v00);
                Ss[(col0 + 1)*72 + kperm(r0)] = __float2half_rn(v01);
                Ss[(col0    )*72 + kperm(r1)] = __float2half_rn(v10);
                Ss[(col0 + 1)*72 + kperm(r1)] = __float2half_rn(v11);
            } else {
                *(__half2*)(Ss + r0*72 + kperm(col0)) = __floats2half2_rn(v00, v01);
                *(__half2*)(Ss + r1*72 + kperm(col0)) = __floats2half2_rn(v10, v11);
            }
        }
        __syncthreads();

        if (which < 2) {
            __half* og = (which == 0 ? g_qh : g_kh) + ((size_t)b*NTOK + h*64)*64;
            for (int idx = tid; idx < 512; idx += 256) {
                int r = idx >> 3, c8 = (idx & 7)*8;
                *(int4*)(og + r*64 + c8) = *(int4*)(Ss + r*72 + c8);
            }
        } else {
            __half* og = g_vTh + (size_t)b*NC*NTOK + h*64;
            for (int idx = tid; idx < 512; idx += 256) {
                int c = idx >> 3, t8 = (idx & 7)*8;
                *(int4*)(og + (size_t)c*NTOK + t8) = *(int4*)(Ss + c*72 + t8);
            }
        }
    }
}

// ---------------------------------------------------------------------------
// Kernel 3: flash attention (R13 layout: 8 warps, 256 thr, 2 CTA/SM).
// Fixed-max exp2 softmax; l accumulated in fp32 on the ALU pipe (end-reduced).
// Fused projection + residual epilogue.
// ---------------------------------------------------------------------------
#define QS_OFF 0
#define KS_OFF (128*SP)
#define VS_OFF (KS_OFF + 3*64*SP)
#define HALF_REGION (VS_OFF + 3*64*SP)          // 40960 halves = 81920 B
#define WP_OFF_B (HALF_REGION*2)
#define ATTN_SMEM (WP_OFF_B + (64*68 + 64)*4)

__global__ void __launch_bounds__(256, 2) attn_kernel(const float* __restrict__ x,
                                                      const float* __restrict__ Wp,
                                                      const float* __restrict__ bp,
                                                      float* __restrict__ out) {
    extern __shared__ __half smh[];
    uint32_t sb = smem_u32(smh);
    __half* Qs = smh + QS_OFF;
    float* Wps = (float*)((char*)smh + WP_OFF_B);      // [64][68]
    float* bps = Wps + 64*68;

    int b  = blockIdx.y;
    int q0 = blockIdx.x * 128;
    int tid = threadIdx.x;
    int lane = tid & 31, warp = tid >> 5;
    int wm = warp * 16;
    int gi = lane >> 2;
    int t4 = lane & 3;

    const __half* qb = g_qh  + ((size_t)b*NTOK + q0)*64;
    const __half* kb = g_kh  + (size_t)b*NTOK*64;
    const __half* vb = g_vTh + (size_t)b*NC*NTOK;

    // ---- Prologue group A: Q + Wp + bp + K0/V0
    for (int idx = tid; idx < 1024; idx += 256) {
        int r = idx >> 3, cB = (idx & 7)*16;
        cp_async16(sb + (QS_OFF + r*SP)*2 + cB, qb + r*64 + cB/2);
    }
    for (int idx = tid; idx < 1024; idx += 256) {
        int r = idx >> 4, ch = idx & 15;
        cp_async16(sb + WP_OFF_B + r*68*4 + ch*16, Wp + r*64 + ch*4);
    }
    if (tid < 16) cp_async16(sb + WP_OFF_B + 64*68*4 + tid*16, bp + tid*4);
    for (int idx = tid; idx < 1024; idx += 256) {
        int r = (idx >> 3) & 63, cB = (idx & 7)*16;
        if (idx < 512)
            cp_async16(sb + (KS_OFF + r*SP)*2 + cB, kb + (size_t)r*64 + cB/2);
        else
            cp_async16(sb + (VS_OFF + r*SP)*2 + cB, vb + (size_t)r*NTOK + cB/2);
    }
    CP_COMMIT();
    // ---- Prologue group B: K1/V1
    for (int idx = tid; idx < 1024; idx += 256) {
        int r = (idx >> 3) & 63, cB = (idx & 7)*16;
        if (idx < 512)
            cp_async16(sb + (KS_OFF + 64*SP + r*SP)*2 + cB, kb + (size_t)(64 + r)*64 + cB/2);
        else
            cp_async16(sb + (VS_OFF + 64*SP + r*SP)*2 + cB, vb + (size_t)r*NTOK + 64 + cB/2);
    }
    CP_COMMIT();

    float o[8][4];
    #pragma unroll
    for (int j = 0; j < 8; j++) { o[j][0]=0.f; o[j][1]=0.f; o[j][2]=0.f; o[j][3]=0.f; }
    float l0 = 0.f, l1 = 0.f;      // fp32 partial row sums (quad-reduced at end)

    for (int kt = 0; kt < 64; ++kt) {
        CP_WAIT1();
        __syncthreads();

        if (kt + 2 < 64) {
            const __half* kp = kb + (size_t)((kt+2)*64)*64;
            const __half* vp = vb + (kt+2)*64;
            int buf = (kt + 2) % 3;
            for (int idx = tid; idx < 1024; idx += 256) {
                int r = (idx >> 3) & 63, cB = (idx & 7)*16;
                if (idx < 512)
                    cp_async16(sb + (KS_OFF + buf*64*SP + r*SP)*2 + cB, kp + (size_t)r*64 + cB/2);
                else
                    cp_async16(sb + (VS_OFF + buf*64*SP + r*SP)*2 + cB, vp + (size_t)r*NTOK + cB/2);
            }
        }
        CP_COMMIT();

        const __half* Kb = smh + KS_OFF + (kt % 3)*64*SP;
        const __half* Vb = smh + VS_OFF + (kt % 3)*64*SP;

        // ---- S = Q K^T (scores already in exp2 domain)
        float s[8][4];
        #pragma unroll
        for (int j = 0; j < 8; j++) { s[j][0]=0.f; s[j][1]=0.f; s[j][2]=0.f; s[j][3]=0.f; }
        #pragma unroll
        for (int k = 0; k < 4; ++k) {
            int off = k*16 + 4*t4;
            uint2 a0 = *(const uint2*)(Qs + (wm + gi)*SP + off);
            uint2 a1 = *(const uint2*)(Qs + (wm + gi + 8)*SP + off);
            #pragma unroll
            for (int j = 0; j < 8; ++j) {
                uint2 bb = *(const uint2*)(Kb + (j*8 + gi)*SP + off);
                mma_f16(s[j], a0.x, a1.x, a0.y, a1.y, bb.x, bb.y);
            }
        }

        // ---- P = exp2(S) -> half2 A-frags; l accumulated in fp32 (ALU pipe)
        uint32_t pa[8][2];
        #pragma unroll
        for (int j = 0; j < 8; j++) {
            __half2 h0 = __floats2half2_rn(s[j][0], s[j][1]);
            __half2 h1 = __floats2half2_rn(s[j][2], s[j][3]);
            pa[j][0] = ex2h2(*(uint32_t*)&h0);
            pa[j][1] = ex2h2(*(uint32_t*)&h1);
            float2 f0 = __half22float2(*(__half2*)&pa[j][0]);
            float2 f1 = __half22float2(*(__half2*)&pa[j][1]);
            l0 += f0.x + f0.y;
            l1 += f1.x + f1.y;
        }

        // ---- O += P V
        #pragma unroll
        for (int jj = 0; jj < 4; ++jj) {
            int off = jj*16 + 4*t4;
            #pragma unroll
            for (int jc = 0; jc < 8; ++jc) {
                uint2 bb = *(const uint2*)(Vb + (jc*8 + gi)*SP + off);
                mma_f16(o[jc], pa[2*jj][0], pa[2*jj][1], pa[2*jj+1][0], pa[2*jj+1][1], bb.x, bb.y);
            }
        }
    }

    // quad-reduce l (cols 2t4,2t4+1 over 4 quad threads -> full 64-token sums)
    l0 += __shfl_xor_sync(0xffffffffu, l0, 1);
    l0 += __shfl_xor_sync(0xffffffffu, l0, 2);
    l1 += __shfl_xor_sync(0xffffffffu, l1, 1);
    l1 += __shfl_xor_sync(0xffffffffu, l1, 2);

    // ================= fused projection + residual epilogue =================
    float* As = (float*)smh;             // [128][68] overlays Q/K rings

    float rl0 = 1.f / l0, rl1 = 1.f / l1;
    __syncthreads();
    #pragma unroll
    for (int j = 0; j < 8; j++) {
        int c = j*8 + 2*t4;
        *(float2*)(As + (wm + gi)*68 + c)     = make_float2(o[j][0]*rl0, o[j][1]*rl0);
        *(float2*)(As + (wm + gi + 8)*68 + c) = make_float2(o[j][2]*rl1, o[j][3]*rl1);
    }
    __syncthreads();

    int ty = tid >> 4, tx = tid & 15;
    int h0 = q0 >> 6;
    #pragma unroll
    for (int hs = 0; hs < 2; ++hs) {
        float acc[4][4];
        #pragma unroll
        for (int i = 0; i < 4; i++)
            #pragma unroll
            for (int j = 0; j < 4; j++) acc[i][j] = 0.f;

        #pragma unroll 16
        for (int w = 0; w < 64; ++w) {
            float a[4], bb[4];
            #pragma unroll
            for (int i = 0; i < 4; i++) a[i] = As[(hs*64 + w)*68 + (ty + 16*i)];
            #pragma unroll
            for (int j = 0; j < 4; j++) { int jj = tx + 16*j; bb[j] = Wps[jj*68 + w]; }
            #pragma unroll
            for (int i = 0; i < 4; i++)
                #pragma unroll
                for (int j = 0; j < 4; j++) acc[i][j] += a[i]*bb[j];
        }

        int h = h0 + hs;
        #pragma unroll
        for (int j = 0; j < 4; j++) {
            int jj = tx + 16*j;
            float bias = bps[jj];
            #pragma unroll
            for (int i = 0; i < 4; i++) {
                int cc = ty + 16*i;
                size_t oidx = (((size_t)b*64 + cc)*64 + h)*64 + jj;
                out[oidx] = acc[i][j] + bias + x[oidx];
            }
        }
    }
}

// ---------------------------------------------------------------------------
extern "C" void kernel_launch(void* const* d_in, const int* in_sizes, int n_in,
                              void* d_out, int out_size) {
    const float* x   = (const float*)d_in[0];
    const float* gnw = (const float*)d_in[1];
    const float* gnb = (const float*)d_in[2];
    const float* Wq  = (const float*)d_in[3];
    const float* bq  = (const float*)d_in[4];
    const float* Wk  = (const float*)d_in[5];
    const float* bk  = (const float*)d_in[6];
    const float* Wv  = (const float*)d_in[7];
    const float* bv  = (const float*)d_in[8];
    const float* Wp  = (const float*)d_in[9];
    const float* bp  = (const float*)d_in[10];
    float* out = (float*)d_out;

    cudaFuncSetAttribute(attn_kernel, cudaFuncAttributeMaxDynamicSharedMemorySize, ATTN_SMEM);

    gn_stats_kernel<<<NB*NGROUPS, 256>>>(x);
    qkv_kernel<<<NB*NH, 256>>>(x, gnw, gnb, Wq, bq, Wk, bk, Wv, bv);
    attn_kernel<<<dim3(NTOK/128, NB), 256, ATTN_SMEM>>>(x, Wp, bp, out);
}